// round 12
// baseline (speedup 1.0000x reference)
#include <cuda_runtime.h>
#include <cuda_fp16.h>
#include <cstdint>

#define D    128
#define NMAX 50000
#define EMAX 800000
#define NBMAX 64   // ceil(NMAX/1024)=49
#define BFLAG 0x40000000
#define WCHUNK 2304   // half2 per W chunk: 2 parts * 128 n * 9 (padded kp)

// ---------------- scratch (device globals: allocation-free) ----------------
__device__ __align__(16) __half g_Ah[(size_t)NMAX * D];   // h_lin' / hm' (fp16, dis-scaled)
__device__ __align__(16) __half g_Bh[(size_t)NMAX * D];   // h post-relu (fp16)
__device__ __align__(16) __half2 g_W1s[8 * WCHUNK];       // split w1, smem-tile layout
__device__ __align__(16) __half2 g_W2s[8 * WCHUNK];       // split [w_mu|w_ls]
__device__ int   g_degi[NMAX];    // zero at module load; re-zeroed by k_gather_out
__device__ float g_dis[NMAX];
__device__ int   g_off[NMAX];
__device__ int   g_cur[NMAX];
__device__ int   g_bsum[NBMAX];   // published block totals (value | BFLAG)
__device__ int   g_eidx[EMAX];    // CSR-ordered src indices (norm factored out)
__device__ int   g_is32;

// ------- init: pre-split W for both layers + dtype detect + bsum clear -------
// Layout matches smem Bs exactly: idx = kc*2304 + p*1152 + n*9 + kp
__global__ void k_init(const long long* __restrict__ ei, int E, int n,
                       const float* __restrict__ w1,
                       const float* __restrict__ wmu, const float* __restrict__ wls) {
    int i = blockIdx.x * blockDim.x + threadIdx.x;
    if (i < 16384) {            // 2 layers * 8 kc * 128 n * 8 kp
        int layer = i >> 13;
        int rem = i & 8191;
        int kc = rem >> 10;
        int r2 = rem & 1023;
        int nn = r2 >> 3;
        int kp = r2 & 7;
        int k = kc * 16 + 2 * kp;
        float w0, wv1;
        if (layer == 0) {
            w0  = w1[(size_t)k * 128 + nn];
            wv1 = w1[(size_t)(k + 1) * 128 + nn];
        } else {
            if (nn < 64) { w0 = wmu[k * 64 + nn];      wv1 = wmu[(k + 1) * 64 + nn]; }
            else         { w0 = wls[k * 64 + nn - 64]; wv1 = wls[(k + 1) * 64 + nn - 64]; }
        }
        __half h0 = __float2half_rn(w0), h1 = __float2half_rn(wv1);
        __half2* dst = (layer == 0) ? g_W1s : g_W2s;
        int base = kc * WCHUNK + nn * 9 + kp;
        dst[base] = __halves2half2(h0, h1);                       // hi part (p=0)
        dst[base + 1152] = __halves2half2(                        // lo part (p=1)
            __float2half_rn(w0 - __half2float(h0)),
            __float2half_rn(wv1 - __half2float(h1)));
    }
    if (blockIdx.x == 0) {
        if (threadIdx.x < NBMAX) g_bsum[threadIdx.x] = 0;
        __shared__ int bad;
        if (threadIdx.x == 0) bad = 0;
        __syncthreads();
        int lim = E < 1024 ? E : 1024;
        for (int k = threadIdx.x; k < lim; k += blockDim.x) {
            long long v = ei[k];
            if (v < 0 || v >= (long long)n) bad = 1;
        }
        __syncthreads();
        if (threadIdx.x == 0) g_is32 = bad;
    }
}

// decode dst straight from edge_index, histogram degrees
__global__ void k_deg(const void* __restrict__ ei, int E) {
    int i = blockIdx.x * blockDim.x + threadIdx.x;
    if (i < E) {
        int d = g_is32 ? ((const int*)ei)[E + i]
                       : (int)((const long long*)ei)[(size_t)E + i];
        atomicAdd(&g_degi[d], 1);
    }
}

// ---- single-kernel scan: local shuffle scan + cross-block lookback ----
__global__ void k_scan(int n) {
    __shared__ int ws[32];
    __shared__ int stot;
    __shared__ int spre;
    int t = threadIdx.x;
    int lane = t & 31, warp = t >> 5;
    int i = blockIdx.x * 1024 + t;
    int d = (i < n) ? g_degi[i] : 0;
    int v = d;
#pragma unroll
    for (int o = 1; o < 32; o <<= 1) {
        int u = __shfl_up_sync(0xFFFFFFFF, v, o);
        if (lane >= o) v += u;
    }
    if (lane == 31) ws[warp] = v;
    if (t == 0) spre = 0;
    __syncthreads();
    if (warp == 0) {
        int s = ws[lane];
#pragma unroll
        for (int o = 1; o < 32; o <<= 1) {
            int u = __shfl_up_sync(0xFFFFFFFF, s, o);
            if (lane >= o) s += u;
        }
        ws[lane] = s;
    }
    __syncthreads();
    int incl = v + ((warp > 0) ? ws[warp - 1] : 0);
    if (t == 1023) stot = incl;
    __syncthreads();
    if (t == 0) atomicExch(&g_bsum[blockIdx.x], stot | BFLAG);
    if (t < blockIdx.x) {
        volatile int* vb = g_bsum;
        int pv;
        do { pv = vb[t]; } while (!(pv & BFLAG));
        atomicAdd(&spre, pv & ~BFLAG);
    }
    __syncthreads();
    if (i < n) {
        int o = spre + incl - d;
        g_off[i] = o;
        g_cur[i] = o;
        g_dis[i] = (d > 0) ? rsqrtf((float)d) : 0.0f;
    }
}

// ---------------- fp16 MMA helper ----------------
__device__ __forceinline__ void mma_f16(float* c, const uint32_t* a,
                                        uint32_t b0, uint32_t b1) {
    asm volatile(
        "mma.sync.aligned.m16n8k16.row.col.f32.f16.f16.f32 "
        "{%0,%1,%2,%3}, {%4,%5,%6,%7}, {%8,%9}, {%0,%1,%2,%3};"
        : "+f"(c[0]), "+f"(c[1]), "+f"(c[2]), "+f"(c[3])
        : "r"(a[0]), "r"(a[1]), "r"(a[2]), "r"(a[3]), "r"(b0), "r"(b1));
}

// ------ GEMM body: OUT[r,:] = dis[r] * (X[r,:] @ W), fp16 out, 2 passes -----
// W pre-split into hi/lo (Wsp). AF32: A from fp32 (single fp16 rounding).
template <bool AF32>
__device__ __forceinline__ void gemm_body(int bid, const void* __restrict__ Xv,
                                          const __half2* __restrict__ Wsp,
                                          __half* __restrict__ OUT, int nrows) {
    __shared__ __half2 Bs[2][128][9];
    __shared__ __half2 As[128][9];

    int tx = threadIdx.x;
    int lane = tx & 31, wp = tx >> 5;
    int g = lane >> 2, t = lane & 3;
    int rowBase = bid * 128;
    int wr = wp * 16;

    float c[16][4];
#pragma unroll
    for (int j = 0; j < 16; j++) {
        c[j][0] = 0.f; c[j][1] = 0.f; c[j][2] = 0.f; c[j][3] = 0.f;
    }

    for (int kc = 0; kc < 8; kc++) {
        int k0 = kc * 16;
        // W chunk: straight uint4 copy of the precomputed split tile (9216 B)
        {
            const uint4* src = (const uint4*)(Wsp + (size_t)kc * WCHUNK);
            uint4* dst = (uint4*)&Bs[0][0][0];
            for (int q = tx; q < 576; q += 256) dst[q] = src[q];
        }
        // X chunk: 128 rows x 16 k
#pragma unroll
        for (int it = 0; it < 2; it++) {
            int q = tx + it * 256;
            int row = q >> 2, j4 = q & 3;
            int grow = rowBase + row;
            if (AF32) {
                float4 v = (grow < nrows)
                           ? ((const float4*)((const float*)Xv + (size_t)grow * 128 + k0))[j4]
                           : make_float4(0.f, 0.f, 0.f, 0.f);
                As[row][j4 * 2 + 0] = __floats2half2_rn(v.x, v.y);
                As[row][j4 * 2 + 1] = __floats2half2_rn(v.z, v.w);
            } else {
                uint2 u = (grow < nrows)
                          ? ((const uint2*)((const __half*)Xv + (size_t)grow * 128 + k0))[j4]
                          : make_uint2(0u, 0u);
                As[row][j4 * 2 + 0] = *(__half2*)&u.x;
                As[row][j4 * 2 + 1] = *(__half2*)&u.y;
            }
        }
        __syncthreads();

        uint32_t A0[4];
        A0[0] = *(uint32_t*)&As[wr + g][t];
        A0[1] = *(uint32_t*)&As[wr + g + 8][t];
        A0[2] = *(uint32_t*)&As[wr + g][t + 4];
        A0[3] = *(uint32_t*)&As[wr + g + 8][t + 4];
#pragma unroll
        for (int j = 0; j < 16; j++) {
            uint32_t bh0 = *(uint32_t*)&Bs[0][j * 8 + g][t];
            uint32_t bh1 = *(uint32_t*)&Bs[0][j * 8 + g][t + 4];
            uint32_t bl0 = *(uint32_t*)&Bs[1][j * 8 + g][t];
            uint32_t bl1 = *(uint32_t*)&Bs[1][j * 8 + g][t + 4];
            mma_f16(c[j], A0, bh0, bh1);   // A * Wh
            mma_f16(c[j], A0, bl0, bl1);   // A * Wl
        }
        __syncthreads();
    }

    int r0 = rowBase + wr + g;
    int r1 = r0 + 8;
    float d0 = (r0 < nrows) ? g_dis[r0] : 0.f;
    float d1 = (r1 < nrows) ? g_dis[r1] : 0.f;
#pragma unroll
    for (int j = 0; j < 16; j++) {
        int col = j * 8 + 2 * t;
        if (r0 < nrows)
            *(__half2*)(OUT + (size_t)r0 * 128 + col) =
                __floats2half2_rn(c[j][0] * d0, c[j][1] * d0);
        if (r1 < nrows)
            *(__half2*)(OUT + (size_t)r1 * 128 + col) =
                __floats2half2_rn(c[j][2] * d1, c[j][3] * d1);
    }
}

// ---------------- fused: CSR fill || GEMM1, roles striped for co-residency ----
__global__ void __launch_bounds__(256, 2)
k_fill_gemm1(const void* __restrict__ ei, int E, int fillBlocks,
             const float* __restrict__ X, __half* __restrict__ OUT, int nrows) {
    int bid = blockIdx.x;
    bool isFill;
    int idx;
    if (bid < 2 * fillBlocks) {
        isFill = (bid & 1);
        idx = bid >> 1;
    } else {
        isFill = false;
        idx = fillBlocks + (bid - 2 * fillBlocks);
    }
    if (isFill) {
        int stride = fillBlocks * 256;
        for (int i = idx * 256 + threadIdx.x; i < E; i += stride) {
            int s, d;
            if (g_is32) {
                const int* p = (const int*)ei;
                s = p[i]; d = p[E + i];
            } else {
                const long long* p = (const long long*)ei;
                s = (int)p[i]; d = (int)p[(size_t)E + i];
            }
            int pos = atomicAdd(&g_cur[d], 1);
            g_eidx[pos] = s;
        }
        return;
    }
    gemm_body<true>(idx, X, g_W1s, OUT, nrows);
}

// plain GEMM2 wrapper (fp16 A, exact)
__global__ void __launch_bounds__(256, 2)
k_gemm2(const __half* __restrict__ X, __half* __restrict__ OUT, int nrows) {
    gemm_body<false>(blockIdx.x, X, g_W2s, OUT, nrows);
}

// ---------------- warp-per-node gathers (norm factored into gemm + node) -----
__global__ void k_gather_relu(const __half* __restrict__ h, __half* __restrict__ out,
                              const float* __restrict__ b1, int n) {
    int w = (blockIdx.x * blockDim.x + threadIdx.x) >> 5;
    int lane = threadIdx.x & 31;
    if (w >= n) return;
    int start = g_off[w], deg = g_degi[w];
    float4 acc = make_float4(0.f, 0.f, 0.f, 0.f);
#pragma unroll 4
    for (int i = 0; i < deg; i++) {
        int s = __ldg(&g_eidx[start + i]);
        uint2 u = ((const uint2*)(h + (size_t)s * 128))[lane];
        float2 v0 = __half22float2(*(__half2*)&u.x);
        float2 v1 = __half22float2(*(__half2*)&u.y);
        acc.x += v0.x; acc.y += v0.y;
        acc.z += v1.x; acc.w += v1.y;
    }
    float dw = g_dis[w];
    float4 b = ((const float4*)b1)[lane];
    acc.x = fmaxf(acc.x * dw + b.x, 0.f);
    acc.y = fmaxf(acc.y * dw + b.y, 0.f);
    acc.z = fmaxf(acc.z * dw + b.z, 0.f);
    acc.w = fmaxf(acc.w * dw + b.w, 0.f);
    uint2 o;
    *(__half2*)&o.x = __floats2half2_rn(acc.x, acc.y);
    *(__half2*)&o.y = __floats2half2_rn(acc.z, acc.w);
    ((uint2*)(out + (size_t)w * 128))[lane] = o;
}

// Layer 2 gather; epilogue re-zeroes g_degi[w] for the next call.
__global__ void k_gather_out(const __half* __restrict__ h, float* __restrict__ out,
                             const float* __restrict__ bmu, const float* __restrict__ bls,
                             int half, int n) {
    int w = (blockIdx.x * blockDim.x + threadIdx.x) >> 5;
    int lane = threadIdx.x & 31;
    if (w >= n) return;
    int start = g_off[w], deg = g_degi[w];
    float4 acc = make_float4(0.f, 0.f, 0.f, 0.f);
#pragma unroll 4
    for (int i = 0; i < deg; i++) {
        int s = __ldg(&g_eidx[start + i]);
        uint2 u = ((const uint2*)(h + (size_t)s * 128))[lane];
        float2 v0 = __half22float2(*(__half2*)&u.x);
        float2 v1 = __half22float2(*(__half2*)&u.y);
        acc.x += v0.x; acc.y += v0.y;
        acc.z += v1.x; acc.w += v1.y;
    }
    if (lane == 0) g_degi[w] = 0;   // reset for next launch
    float dw = g_dis[w];
    int col = lane * 4;
    float4 b; float* p;
    if (col < 64) {
        b = ((const float4*)bmu)[lane];
        p = out + (size_t)w * 64 + col;
    } else {
        b = ((const float4*)bls)[lane - 16];
        p = out + half + (size_t)w * 64 + (col - 64);
    }
    acc.x = acc.x * dw + b.x; acc.y = acc.y * dw + b.y;
    acc.z = acc.z * dw + b.z; acc.w = acc.w * dw + b.w;
    *(float4*)p = acc;
}

// ---------------- launch ----------------
extern "C" void kernel_launch(void* const* d_in, const int* in_sizes, int n_in,
                              void* d_out, int out_size) {
    const float* x   = (const float*)d_in[0];
    const void*  ei  = d_in[1];
    const float* w1  = (const float*)d_in[2];
    const float* b1  = (const float*)d_in[3];
    const float* wmu = (const float*)d_in[4];
    const float* bmu = (const float*)d_in[5];
    const float* wls = (const float*)d_in[6];
    const float* bls = (const float*)d_in[7];
    float* out = (float*)d_out;

    int n = in_sizes[0] / D;          // 50000
    int E = in_sizes[1] / 2;          // 800000
    int half = out_size / 2;          // n*64

    __half *Ah, *Bh;
    cudaGetSymbolAddress((void**)&Ah, g_Ah);
    cudaGetSymbolAddress((void**)&Bh, g_Bh);

    const int T = 256;
    int nb = (n + 1023) / 1024;       // 49 <= NBMAX, all co-resident
    int gemmBlocks = (n + 127) / 128;
    int fillBlocks = 256;
    int gatherBlocks = (n * 32 + T - 1) / T;

    // W pre-split (both layers) + dtype detect + bsum-flag clear
    k_init<<<64, T>>>((const long long*)ei, E, n, w1, wmu, wls);
    // degree histogram (degi pre-zeroed by previous call's k_gather_out)
    k_deg<<<(E + T - 1) / T, T>>>(ei, E);
    // fused exclusive scan (off/cur/dis) with cross-block lookback
    k_scan<<<nb, 1024>>>(n);
    // CSR fill || GEMM1 (h_lin' = dis .* (x @ w1)), striped roles
    k_fill_gemm1<<<fillBlocks + gemmBlocks, T>>>(ei, E, fillBlocks, x, Ah, n);
    // layer 1 aggregate
    k_gather_relu<<<gatherBlocks, T>>>(Ah, Bh, b1, n);
    // layer 2: hm' = dis .* (h @ [w_mu|w_ls]) ; aggregate into split output
    k_gemm2<<<gemmBlocks, T>>>(Bh, Ah, n);
    k_gather_out<<<gatherBlocks, T>>>(Ah, out, bmu, bls, half, n);
}

// round 15
// speedup vs baseline: 1.0445x; 1.0445x over previous
#include <cuda_runtime.h>
#include <cuda_fp16.h>
#include <cstdint>

#define D    128
#define NMAX 50000
#define EMAX 800000
#define NBMAX 64   // ceil(NMAX/1024)=49
#define BFLAG 0x40000000

// ---------------- scratch (device globals: allocation-free) ----------------
__device__ __align__(16) __half g_Ah[(size_t)NMAX * D];   // h_lin' / hm' (fp16, dis-scaled)
__device__ __align__(16) __half g_Bh[(size_t)NMAX * D];   // h post-relu (fp16)
__device__ __align__(16) float  g_Wcat[D * D];            // [w_mu | w_ls]
__device__ int   g_degi[NMAX];    // zero at module load; re-zeroed by k_gather_out
__device__ float g_dis[NMAX];
__device__ int   g_off[NMAX];
__device__ int   g_cur[NMAX];
__device__ int   g_bsum[NBMAX];   // published block totals (value | BFLAG)
__device__ int   g_eidx[EMAX];    // CSR-ordered src indices (norm factored out)
__device__ int   g_is32;

// ------- init: Wcat concat + dtype detect + clear bsum flags -------
__global__ void k_init(const long long* __restrict__ ei, int E, int n,
                       const float* __restrict__ wmu, const float* __restrict__ wls) {
    int i = blockIdx.x * blockDim.x + threadIdx.x;
    if (i < D * D) {
        int k = i >> 7, c = i & 127;
        g_Wcat[i] = (c < 64) ? wmu[k * 64 + c] : wls[k * 64 + (c - 64)];
    }
    if (blockIdx.x == 0) {
        if (threadIdx.x < NBMAX) g_bsum[threadIdx.x] = 0;
        __shared__ int bad;
        if (threadIdx.x == 0) bad = 0;
        __syncthreads();
        int lim = E < 1024 ? E : 1024;
        for (int k = threadIdx.x; k < lim; k += blockDim.x) {
            long long v = ei[k];
            if (v < 0 || v >= (long long)n) bad = 1;
        }
        __syncthreads();
        if (threadIdx.x == 0) g_is32 = bad;
    }
}

// decode dst straight from edge_index, histogram degrees
__global__ void k_deg(const void* __restrict__ ei, int E) {
    int i = blockIdx.x * blockDim.x + threadIdx.x;
    if (i < E) {
        int d = g_is32 ? ((const int*)ei)[E + i]
                       : (int)((const long long*)ei)[(size_t)E + i];
        atomicAdd(&g_degi[d], 1);
    }
}

// ---- single-kernel scan: local shuffle scan + cross-block lookback ----
__global__ void k_scan(int n) {
    __shared__ int ws[32];
    __shared__ int stot;
    __shared__ int spre;
    int t = threadIdx.x;
    int lane = t & 31, warp = t >> 5;
    int i = blockIdx.x * 1024 + t;
    int d = (i < n) ? g_degi[i] : 0;
    int v = d;
#pragma unroll
    for (int o = 1; o < 32; o <<= 1) {
        int u = __shfl_up_sync(0xFFFFFFFF, v, o);
        if (lane >= o) v += u;
    }
    if (lane == 31) ws[warp] = v;
    if (t == 0) spre = 0;
    __syncthreads();
    if (warp == 0) {
        int s = ws[lane];
#pragma unroll
        for (int o = 1; o < 32; o <<= 1) {
            int u = __shfl_up_sync(0xFFFFFFFF, s, o);
            if (lane >= o) s += u;
        }
        ws[lane] = s;
    }
    __syncthreads();
    int incl = v + ((warp > 0) ? ws[warp - 1] : 0);
    if (t == 1023) stot = incl;
    __syncthreads();
    if (t == 0) atomicExch(&g_bsum[blockIdx.x], stot | BFLAG);
    if (t < blockIdx.x) {
        volatile int* vb = g_bsum;
        int pv;
        do { pv = vb[t]; } while (!(pv & BFLAG));
        atomicAdd(&spre, pv & ~BFLAG);
    }
    __syncthreads();
    if (i < n) {
        int o = spre + incl - d;
        g_off[i] = o;
        g_cur[i] = o;
        g_dis[i] = (d > 0) ? rsqrtf((float)d) : 0.0f;
    }
}

// ---------------- fp16 MMA helper ----------------
__device__ __forceinline__ void mma_f16(float* c, const uint32_t* a,
                                        uint32_t b0, uint32_t b1) {
    asm volatile(
        "mma.sync.aligned.m16n8k16.row.col.f32.f16.f16.f32 "
        "{%0,%1,%2,%3}, {%4,%5,%6,%7}, {%8,%9}, {%0,%1,%2,%3};"
        : "+f"(c[0]), "+f"(c[1]), "+f"(c[2]), "+f"(c[3])
        : "r"(a[0]), "r"(a[1]), "r"(a[2]), "r"(a[3]), "r"(b0), "r"(b1));
}

// ---- GEMM body: OUT[r,:] = dis[r] * (X[r,:] @ W), fp16 out ----
// 512 threads, 128x128 block tile, warp tile m16 x n64 (16 warps).
// PASSES==2: X fp16 (exact A). PASSES==3: X fp32 split into fp16 hi+lo.
template <int PASSES, typename IT>
__device__ __forceinline__ void gemm_body(int bid, const IT* __restrict__ Xv,
                                          const float* __restrict__ W,
                                          __half* __restrict__ OUT, int nrows) {
    __shared__ __half2 Bs[2][128][9];
    __shared__ __half2 As[(PASSES == 3) ? 2 : 1][128][9];

    int tx = threadIdx.x;
    int lane = tx & 31, wp = tx >> 5;          // 16 warps
    int g = lane >> 2, t = lane & 3;
    int rowBase = bid * 128;
    int wr = (wp >> 1) * 16;                    // warp row group
    int jbase = (wp & 1) * 8;                   // warp col half (8 n-tiles)

    float c[8][4];
#pragma unroll
    for (int j = 0; j < 8; j++) {
        c[j][0] = 0.f; c[j][1] = 0.f; c[j][2] = 0.f; c[j][3] = 0.f;
    }

    for (int kc = 0; kc < 8; kc++) {
        int k0 = kc * 16;
        // stage W: 8 k-pairs x 128 n = 1024 entries, hi+lo split
#pragma unroll
        for (int it = 0; it < 2; it++) {
            int q = tx + it * 512;
            int nn = q & 127, kp = q >> 7;
            float w0 = W[(size_t)(k0 + 2 * kp) * 128 + nn];
            float w1 = W[(size_t)(k0 + 2 * kp + 1) * 128 + nn];
            __half h0 = __float2half_rn(w0), h1 = __float2half_rn(w1);
            Bs[0][nn][kp] = __halves2half2(h0, h1);
            Bs[1][nn][kp] = __halves2half2(
                __float2half_rn(w0 - __half2float(h0)),
                __float2half_rn(w1 - __half2float(h1)));
        }
        // stage X: 128 rows x 16 k = 512 float4/uint2 slots
        {
            int row = tx >> 2, j4 = tx & 3;
            int grow = rowBase + row;
            if (PASSES == 2) {
                uint2 u = (grow < nrows)
                          ? ((const uint2*)((const __half*)Xv + (size_t)grow * 128 + k0))[j4]
                          : make_uint2(0u, 0u);
                As[0][row][j4 * 2 + 0] = *(__half2*)&u.x;
                As[0][row][j4 * 2 + 1] = *(__half2*)&u.y;
            } else {
                float4 v = (grow < nrows)
                           ? ((const float4*)((const float*)Xv + (size_t)grow * 128 + k0))[j4]
                           : make_float4(0.f, 0.f, 0.f, 0.f);
                __half hx = __float2half_rn(v.x), hy = __float2half_rn(v.y);
                __half hz = __float2half_rn(v.z), hw = __float2half_rn(v.w);
                As[0][row][j4 * 2 + 0] = __halves2half2(hx, hy);
                As[0][row][j4 * 2 + 1] = __halves2half2(hz, hw);
                As[PASSES == 3 ? 1 : 0][row][j4 * 2 + 0] = __halves2half2(
                    __float2half_rn(v.x - __half2float(hx)),
                    __float2half_rn(v.y - __half2float(hy)));
                As[PASSES == 3 ? 1 : 0][row][j4 * 2 + 1] = __halves2half2(
                    __float2half_rn(v.z - __half2float(hz)),
                    __float2half_rn(v.w - __half2float(hw)));
            }
        }
        __syncthreads();

        uint32_t A0[4], A1[4];
        A0[0] = *(uint32_t*)&As[0][wr + g][t];
        A0[1] = *(uint32_t*)&As[0][wr + g + 8][t];
        A0[2] = *(uint32_t*)&As[0][wr + g][t + 4];
        A0[3] = *(uint32_t*)&As[0][wr + g + 8][t + 4];
        if (PASSES == 3) {
            A1[0] = *(uint32_t*)&As[1][wr + g][t];
            A1[1] = *(uint32_t*)&As[1][wr + g + 8][t];
            A1[2] = *(uint32_t*)&As[1][wr + g][t + 4];
            A1[3] = *(uint32_t*)&As[1][wr + g + 8][t + 4];
        }
#pragma unroll
        for (int j = 0; j < 8; j++) {
            int jj = jbase + j;
            uint32_t bh0 = *(uint32_t*)&Bs[0][jj * 8 + g][t];
            uint32_t bh1 = *(uint32_t*)&Bs[0][jj * 8 + g][t + 4];
            uint32_t bl0 = *(uint32_t*)&Bs[1][jj * 8 + g][t];
            uint32_t bl1 = *(uint32_t*)&Bs[1][jj * 8 + g][t + 4];
            mma_f16(c[j], A0, bh0, bh1);                   // Xh * Wh
            if (PASSES == 3) mma_f16(c[j], A1, bh0, bh1);  // Xl * Wh
            mma_f16(c[j], A0, bl0, bl1);                   // Xh * Wl
        }
        __syncthreads();
    }

    int r0 = rowBase + wr + g;
    int r1 = r0 + 8;
    float d0 = (r0 < nrows) ? g_dis[r0] : 0.f;
    float d1 = (r1 < nrows) ? g_dis[r1] : 0.f;
#pragma unroll
    for (int j = 0; j < 8; j++) {
        int col = (jbase + j) * 8 + 2 * t;
        if (r0 < nrows)
            *(__half2*)(OUT + (size_t)r0 * 128 + col) =
                __floats2half2_rn(c[j][0] * d0, c[j][1] * d0);
        if (r1 < nrows)
            *(__half2*)(OUT + (size_t)r1 * 128 + col) =
                __floats2half2_rn(c[j][2] * d1, c[j][3] * d1);
    }
}

// ---------------- fused: CSR fill || GEMM1, roles striped for co-residency ----
__global__ void __launch_bounds__(512, 2)
k_fill_gemm1_w(const void* __restrict__ ei, int E, int fillBlocks,
               const float* __restrict__ X, const float* __restrict__ W,
               __half* __restrict__ OUT, int nrows) {
    int bid = blockIdx.x;
    bool isFill;
    int idx;
    if (bid < 2 * fillBlocks) {
        isFill = (bid & 1);
        idx = bid >> 1;
    } else {
        isFill = false;
        idx = fillBlocks + (bid - 2 * fillBlocks);
    }
    if (isFill) {
        int stride = fillBlocks * 512;
        for (int i = idx * 512 + threadIdx.x; i < E; i += stride) {
            int s, d;
            if (g_is32) {
                const int* p = (const int*)ei;
                s = p[i]; d = p[E + i];
            } else {
                const long long* p = (const long long*)ei;
                s = (int)p[i]; d = (int)p[(size_t)E + i];
            }
            int pos = atomicAdd(&g_cur[d], 1);
            g_eidx[pos] = s;
        }
        return;
    }
    gemm_body<3, float>(idx, X, W, OUT, nrows);
}

// plain GEMM2 wrapper (fp16 A, exact; W = g_Wcat)
__global__ void __launch_bounds__(512, 2)
k_gemm2(const __half* __restrict__ X, __half* __restrict__ OUT, int nrows) {
    gemm_body<2, __half>(blockIdx.x, X, g_Wcat, OUT, nrows);
}

// ---------------- warp-per-node gathers (norm factored into gemm + node) -----
__global__ void k_gather_relu(const __half* __restrict__ h, __half* __restrict__ out,
                              const float* __restrict__ b1, int n) {
    int w = (blockIdx.x * blockDim.x + threadIdx.x) >> 5;
    int lane = threadIdx.x & 31;
    if (w >= n) return;
    int start = g_off[w], deg = g_degi[w];
    float4 acc = make_float4(0.f, 0.f, 0.f, 0.f);
#pragma unroll 4
    for (int i = 0; i < deg; i++) {
        int s = __ldg(&g_eidx[start + i]);
        uint2 u = ((const uint2*)(h + (size_t)s * 128))[lane];
        float2 v0 = __half22float2(*(__half2*)&u.x);
        float2 v1 = __half22float2(*(__half2*)&u.y);
        acc.x += v0.x; acc.y += v0.y;
        acc.z += v1.x; acc.w += v1.y;
    }
    float dw = g_dis[w];
    float4 b = ((const float4*)b1)[lane];
    acc.x = fmaxf(acc.x * dw + b.x, 0.f);
    acc.y = fmaxf(acc.y * dw + b.y, 0.f);
    acc.z = fmaxf(acc.z * dw + b.z, 0.f);
    acc.w = fmaxf(acc.w * dw + b.w, 0.f);
    uint2 o;
    *(__half2*)&o.x = __floats2half2_rn(acc.x, acc.y);
    *(__half2*)&o.y = __floats2half2_rn(acc.z, acc.w);
    ((uint2*)(out + (size_t)w * 128))[lane] = o;
}

// Layer 2 gather; epilogue re-zeroes g_degi[w] for the next call.
__global__ void k_gather_out(const __half* __restrict__ h, float* __restrict__ out,
                             const float* __restrict__ bmu, const float* __restrict__ bls,
                             int half, int n) {
    int w = (blockIdx.x * blockDim.x + threadIdx.x) >> 5;
    int lane = threadIdx.x & 31;
    if (w >= n) return;
    int start = g_off[w], deg = g_degi[w];
    float4 acc = make_float4(0.f, 0.f, 0.f, 0.f);
#pragma unroll 4
    for (int i = 0; i < deg; i++) {
        int s = __ldg(&g_eidx[start + i]);
        uint2 u = ((const uint2*)(h + (size_t)s * 128))[lane];
        float2 v0 = __half22float2(*(__half2*)&u.x);
        float2 v1 = __half22float2(*(__half2*)&u.y);
        acc.x += v0.x; acc.y += v0.y;
        acc.z += v1.x; acc.w += v1.y;
    }
    if (lane == 0) g_degi[w] = 0;   // reset for next launch
    float dw = g_dis[w];
    int col = lane * 4;
    float4 b; float* p;
    if (col < 64) {
        b = ((const float4*)bmu)[lane];
        p = out + (size_t)w * 64 + col;
    } else {
        b = ((const float4*)bls)[lane - 16];
        p = out + half + (size_t)w * 64 + (col - 64);
    }
    acc.x = acc.x * dw + b.x; acc.y = acc.y * dw + b.y;
    acc.z = acc.z * dw + b.z; acc.w = acc.w * dw + b.w;
    *(float4*)p = acc;
}

// ---------------- launch ----------------
extern "C" void kernel_launch(void* const* d_in, const int* in_sizes, int n_in,
                              void* d_out, int out_size) {
    const float* x   = (const float*)d_in[0];
    const void*  ei  = d_in[1];
    const float* w1  = (const float*)d_in[2];
    const float* b1  = (const float*)d_in[3];
    const float* wmu = (const float*)d_in[4];
    const float* bmu = (const float*)d_in[5];
    const float* wls = (const float*)d_in[6];
    const float* bls = (const float*)d_in[7];
    float* out = (float*)d_out;

    int n = in_sizes[0] / D;          // 50000
    int E = in_sizes[1] / 2;          // 800000
    int half = out_size / 2;          // n*64

    __half *Ah, *Bh;
    cudaGetSymbolAddress((void**)&Ah, g_Ah);
    cudaGetSymbolAddress((void**)&Bh, g_Bh);

    const int T = 256;
    int nb = (n + 1023) / 1024;       // 49 <= NBMAX, all co-resident
    int gemmBlocks = (n + 127) / 128;
    int fillBlocks = 128;             // 128 fill blocks x 512 threads
    int gatherBlocks = (n * 32 + T - 1) / T;

    // Wcat + dtype detect + bsum-flag clear
    k_init<<<(D * D + T - 1) / T, T>>>((const long long*)ei, E, n, wmu, wls);
    // degree histogram (degi pre-zeroed by previous call's k_gather_out)
    k_deg<<<(E + T - 1) / T, T>>>(ei, E);
    // fused exclusive scan (off/cur/dis) with cross-block lookback
    k_scan<<<nb, 1024>>>(n);
    // CSR fill || GEMM1 (h_lin' = dis .* (x @ w1)), striped roles
    k_fill_gemm1_w<<<fillBlocks + gemmBlocks, 512>>>(ei, E, fillBlocks, x, w1, Ah, n);
    // layer 1 aggregate
    k_gather_relu<<<gatherBlocks, T>>>(Ah, Bh, b1, n);
    // layer 2: hm' = dis .* (h @ [w_mu|w_ls]) ; aggregate into split output
    k_gemm2<<<gemmBlocks, 512>>>(Bh, Ah, n);
    k_gather_out<<<gatherBlocks, T>>>(Ah, out, bmu, bls, half, n);
}